// round 14
// baseline (speedup 1.0000x reference)
#include <cuda_runtime.h>
#include <cuda_bf16.h>

#define S 512
#define BB 512
#define T 64

__device__ float g_den[BB];
__device__ float g_num[BB];
__device__ unsigned g_tick = 0;   // wraps via atomicInc; never reset

typedef unsigned long long u64;

__device__ __forceinline__ u64 ffma2(u64 a, u64 b, u64 c) {
    u64 d; asm("fma.rn.f32x2 %0, %1, %2, %3;" : "=l"(d) : "l"(a), "l"(b), "l"(c)); return d;
}
__device__ __forceinline__ u64 fadd2(u64 a, u64 b) {
    u64 d; asm("add.rn.f32x2 %0, %1, %2;" : "=l"(d) : "l"(a), "l"(b)); return d;
}
__device__ __forceinline__ u64 pack2(float x, float y) {
    u64 d; asm("mov.b64 %0, {%1, %2};" : "=l"(d) : "f"(x), "f"(y)); return d;
}
__device__ __forceinline__ float2 unpack2(u64 v) {
    float2 r; asm("mov.b64 {%0, %1}, %2;" : "=f"(r.x), "=f"(r.y) : "l"(v)); return r;
}
__device__ __forceinline__ float wsum(float v) {
#pragma unroll
    for (int o = 16; o; o >>= 1) v += __shfl_xor_sync(0xffffffffu, v, o);
    return v;
}

// ---------------------------------------------------------------------------
// One block = one batch = 4 warps (one per SMSP). Warp w owns output states
// w*16..w*16+15; TWO lanes per state split the 64-input dot product (parity
// p covers inputs [32p, 32p+32)): per lane 8 LDS.128 + 16 FFMA2 + 1 shfl.
// ~4 blocks/SM -> 4 warps/SMSP from 4 independent batches hide all stalls.
// alpha_j = K + log(u_j); scale bookkeeping at chunk starts only; renorm
// published from step-7's u, consumed after step-8's bar.
// ---------------------------------------------------------------------------
__global__ void __launch_bounds__(128, 4) crf_fused(
    const float* __restrict__ em,
    const int*   __restrict__ tags,     // int64 downgraded to int32 by harness
    const int*   __restrict__ mask,     // bool widened to int32 by harness
    const float* __restrict__ trans,
    const float* __restrict__ startT,
    const float* __restrict__ endT,
    float* __restrict__ out)
{
    __shared__ __align__(16) float ubuf[2][T];   // [buf][state]
    __shared__ float spart[2][4];                // [phase][warp] renorm partials
    __shared__ double dpart[4];
    __shared__ unsigned is_last;

    const int warp = threadIdx.x >> 5;   // 0..3
    const int j    = threadIdx.x & 31;
    const int g    = j >> 1;             // state-in-warp 0..15
    const int p    = j & 1;              // input-half parity
    const int o    = warp * 16 + g;      // owned output state
    const int b    = blockIdx.x;

    // E half-column for state o over input pairs [32p .. 32p+31]
    u64 Ecol2[16];
#pragma unroll
    for (int k = 0; k < 16; k++) {
        int i = 32 * p + 2 * k;
        Ecol2[k] = pack2(__expf(trans[i * T + o]),
                         __expf(trans[(i + 1) * T + o]));
    }

    const size_t bT     = (size_t)b * T;
    const size_t stride = (size_t)BB * T;

    // ---- init (s = 0) ----
    float u = __expf(startT[o] + em[bT + o]);
    int buf = 0;
    if (p == 0) ubuf[0][o] = u;
    float pw = wsum(u);                  // counts each state twice
    if (j == 0) spart[0][warp] = pw;
    __syncthreads();

    float U0    = 0.5f * (spart[0][0] + spart[0][1] + spart[0][2] + spart[0][3]);
    float scale = __fdividef(1.0f, U0);  // pending, applied at chunk start
    float pend  = __logf(U0);
    float K     = 0.0f;

    // chunk prefetch registers (steps 1..8 initially)
    float xr[8]; int mr[8];
#pragma unroll
    for (int q = 0; q < 8; q++) {
        int s = 1 + q;
        xr[q] = em[stride * s + bT + o];
        mr[q] = mask[s * BB + b];
    }

    // half-matvec + pair combine
    auto matvec = [&]() -> float {
        const ulonglong2* up =
            reinterpret_cast<const ulonglong2*>(&ubuf[buf][32 * p]);
        u64 a0 = 0, a1 = 0, a2 = 0, a3 = 0;
#pragma unroll
        for (int k = 0; k < 4; k++) {
            ulonglong2 v0 = up[2 * k];
            ulonglong2 v1 = up[2 * k + 1];
            a0 = ffma2(v0.x, Ecol2[4 * k],     a0);
            a1 = ffma2(v0.y, Ecol2[4 * k + 1], a1);
            a2 = ffma2(v1.x, Ecol2[4 * k + 2], a2);
            a3 = ffma2(v1.y, Ecol2[4 * k + 3], a3);
        }
        float2 tt = unpack2(fadd2(fadd2(a0, a1), fadd2(a2, a3)));
        float th = tt.x + tt.y;                      // this half's partial
        return th + __shfl_xor_sync(0xffffffffu, th, 1);
    };

    auto step = [&](float xe, int m, int q, bool renorm_chunk) {
        float t = matvec();
        float n;
        if (q == 0) {                      // chunk start: apply pending renorm
            n = t * (xe * scale);
            u     = m ? n : u;
            K    += m ? pend : 0.0f;
            pend  = m ? 0.0f : pend;
            scale = m ? 1.0f : scale;
        } else {
            n = t * xe;
            u = m ? n : u;
        }
        buf ^= 1;
        if (p == 0) ubuf[buf][o] = u;
        if (q == 6 && renorm_chunk) {      // publish U from step-7's u
            float w = wsum(u);
            if (j == 0) spart[1][warp] = w;
        }
        __syncthreads();
        if (q == 7 && renorm_chunk) {      // consume after step-8's bar
            float U = 0.5f * (spart[1][0] + spart[1][1] + spart[1][2] + spart[1][3]);
            scale *= __fdividef(1.0f, U);
            pend  += __logf(U);
        }
    };

    for (int c = 0; c < 64; c++) {
        float xe[8]; int mm[8];
#pragma unroll
        for (int q = 0; q < 8; q++) { xe[q] = __expf(xr[q]); mm[q] = mr[q]; }
        // burst-prefetch next chunk (fire-and-forget, overlaps 8 steps)
#pragma unroll
        for (int q = 0; q < 8; q++) {
            int s = 9 + 8 * c + q;
            s = (s < S) ? s : (S - 1);
            xr[q] = em[stride * s + bT + o];
            mr[q] = mask[s * BB + b];
        }
        if (c < 63) {
#pragma unroll
            for (int q = 0; q < 8; q++) step(xe[q], mm[q], q, true);
        } else {
#pragma unroll
            for (int q = 0; q < 7; q++) step(xe[q], mm[q], q, false);
        }
    }

    // den = K + pend + log( sum(scale * u * exp(end)) )
    {
        float v = scale * u * __expf(endT[o]);
        float w = wsum(v);                 // double-counted
        if (j == 0) spart[0][warp] = w;
        __syncthreads();
        if (threadIdx.x == 0) {
            float V = 0.5f * (spart[0][0] + spart[0][1] + spart[0][2] + spart[0][3]);
            g_den[b] = K + pend + __logf(V);
        }
    }

    // ---- numerator (warp 0; lane j owns steps 16j..16j+15) ----
    if (warp == 0) {
        int tg[17]; int mk[16];
#pragma unroll
        for (int q = 0; q < 17; q++) {
            int s = 16 * j + q - 1;
            tg[q] = (s >= 0) ? (tags[s * BB + b] & (T - 1)) : 0;
        }
#pragma unroll
        for (int q = 0; q < 16; q++) mk[q] = mask[(16 * j + q) * BB + b];

        float acc = 0.0f;
        int cnt = 0;
#pragma unroll
        for (int q = 0; q < 16; q++) {
            int s = 16 * j + q;
            int t = tg[q + 1];
            cnt += (mk[q] ? 1 : 0);
            float e = em[stride * s + bT + t];
            if (s == 0)       acc += startT[t] + e;
            else if (mk[q])   acc += trans[tg[q] * T + t] + e;
        }
        acc = wsum(acc);
#pragma unroll
        for (int ofs = 16; ofs; ofs >>= 1) cnt += __shfl_xor_sync(0xffffffffu, cnt, ofs);
        if (j == 0) {
            int last = (cnt >= 1) ? (cnt - 1) : 0;
            int lt = tags[last * BB + b] & (T - 1);
            g_num[b] = acc + endT[lt];
        }
    }

    // ---- ticket-elected last block computes the mean ----
    __threadfence();
    __syncthreads();
    if (threadIdx.x == 0) {
        unsigned old;
        asm volatile("atom.global.inc.u32 %0, [%1], %2;"
                     : "=r"(old) : "l"(&g_tick), "r"((unsigned)(gridDim.x - 1))
                     : "memory");
        is_last = (old == gridDim.x - 1) ? 1u : 0u;
    }
    __syncthreads();
    if (is_last) {
        int t = threadIdx.x;
        double v = 0.0;
#pragma unroll
        for (int k = 0; k < 4; k++) {
            int idx = t * 4 + k;
            v += (double)g_num[idx] - (double)g_den[idx];
        }
#pragma unroll
        for (int ofs = 16; ofs; ofs >>= 1) v += __shfl_xor_sync(0xffffffffu, v, ofs);
        if (j == 0) dpart[warp] = v;
        __syncthreads();
        if (t == 0) {
            double tot = dpart[0] + dpart[1] + dpart[2] + dpart[3];
            out[0] = (float)(tot * (1.0 / (double)BB));
        }
    }
}

// ---------------------------------------------------------------------------
extern "C" void kernel_launch(void* const* d_in, const int* in_sizes, int n_in,
                              void* d_out, int out_size)
{
    const float* em     = (const float*)d_in[0];
    const int*   tags   = (const int*)d_in[1];
    const int*   mask   = (const int*)d_in[2];
    const float* startT = (const float*)d_in[3];
    const float* endT   = (const float*)d_in[4];
    const float* trans  = (const float*)d_in[5];

    crf_fused<<<BB, 128>>>(em, tags, mask, trans, startT, endT, (float*)d_out);
}

// round 15
// speedup vs baseline: 1.5004x; 1.5004x over previous
#include <cuda_runtime.h>
#include <cuda_bf16.h>

#define S 512
#define BB 512
#define T 64

__device__ float g_den[BB];
__device__ float g_num[BB];
__device__ unsigned g_tick = 0;   // wraps via atomicInc; never reset

typedef unsigned long long u64;

__device__ __forceinline__ u64 ffma2(u64 a, u64 b, u64 c) {
    u64 d; asm("fma.rn.f32x2 %0, %1, %2, %3;" : "=l"(d) : "l"(a), "l"(b), "l"(c)); return d;
}
__device__ __forceinline__ u64 fadd2(u64 a, u64 b) {
    u64 d; asm("add.rn.f32x2 %0, %1, %2;" : "=l"(d) : "l"(a), "l"(b)); return d;
}
__device__ __forceinline__ u64 pack2(float x, float y) {
    u64 d; asm("mov.b64 %0, {%1, %2};" : "=l"(d) : "f"(x), "f"(y)); return d;
}
__device__ __forceinline__ float2 unpack2(u64 v) {
    float2 r; asm("mov.b64 {%0, %1}, %2;" : "=f"(r.x), "=f"(r.y) : "l"(v)); return r;
}
__device__ __forceinline__ float wsum(float v) {
#pragma unroll
    for (int o = 16; o; o >>= 1) v += __shfl_xor_sync(0xffffffffu, v, o);
    return v;
}

// ---------------------------------------------------------------------------
// One warp per batch; lane j owns output states 2j, 2j+1 (EA/EB columns in
// 128 regs). The u vector is exchanged IN-WARP: 32 shfl broadcasts of the
// packed {u_2r, u_2r+1} pair feed fma.rn.f32x2 directly. No smem, no
// barriers, no syncwarp in the scan. alpha = K + log(u); scale bookkeeping
// at chunk heads; lane-local renorm every 8 steps.
// grid=128 x block=128: 512 warps, 1 per SMSP on 128 SMs.
// ---------------------------------------------------------------------------
__global__ void __launch_bounds__(128, 1) crf_fused(
    const float* __restrict__ em,
    const int*   __restrict__ tags,     // int64 downgraded to int32 by harness
    const int*   __restrict__ mask,     // bool widened to int32 by harness
    const float* __restrict__ trans,
    const float* __restrict__ startT,
    const float* __restrict__ endT,
    float* __restrict__ out)
{
    __shared__ double dpart[4];
    __shared__ unsigned is_last;

    const int warp = threadIdx.x >> 5;
    const int j    = threadIdx.x & 31;      // lane; owns states 2j, 2j+1
    const int b    = blockIdx.x * 4 + warp;

    // EA[r] = {E[2r][2j],   E[2r+1][2j]}
    // EB[r] = {E[2r][2j+1], E[2r+1][2j+1]}
    u64 EA[32], EB[32];
    {
        const float2* tr2 = reinterpret_cast<const float2*>(trans);
#pragma unroll
        for (int r = 0; r < 32; r++) {
            float2 r0 = tr2[(2 * r) * 32 + j];
            float2 r1 = tr2[(2 * r + 1) * 32 + j];
            EA[r] = pack2(__expf(r0.x), __expf(r1.x));
            EB[r] = pack2(__expf(r0.y), __expf(r1.y));
        }
    }

    const size_t bT     = (size_t)b * T;
    const size_t stride = (size_t)BB * T;
    const float2* em2base = reinterpret_cast<const float2*>(em + bT);
    const long em2stride = (long)(stride / 2);

    // ---- init (s = 0) ----
    float2 st0 = reinterpret_cast<const float2*>(startT)[j];
    float2 e0  = em2base[j];
    float u0 = __expf(st0.x + e0.x);
    float u1 = __expf(st0.y + e0.y);
    u64 up = pack2(u0, u1);

    float U0    = wsum(u0 + u1);
    float scale = __fdividef(1.0f, U0);   // pending, applied at chunk start
    float pend  = __logf(U0);
    float K     = 0.0f;

    // chunk prefetch (steps 1..8)
    float2 xr[8]; int mr[8];
#pragma unroll
    for (int q = 0; q < 8; q++) {
        int s = 1 + q;
        xr[q] = em2base[(long)s * em2stride + j];
        mr[q] = mask[s * BB + b];
    }

    // shfl-exchange matvec: tA/tB for the two owned output states
    auto matvec = [&](float& tA, float& tB) {
        u64 a0 = 0, a1 = 0, a2 = 0, a3 = 0;
        u64 c0 = 0, c1 = 0, c2 = 0, c3 = 0;
#pragma unroll
        for (int r = 0; r < 32; r += 4) {
            u64 p0 = __shfl_sync(0xffffffffu, up, r);
            u64 p1 = __shfl_sync(0xffffffffu, up, r + 1);
            u64 p2 = __shfl_sync(0xffffffffu, up, r + 2);
            u64 p3 = __shfl_sync(0xffffffffu, up, r + 3);
            a0 = ffma2(p0, EA[r],     a0);
            c0 = ffma2(p0, EB[r],     c0);
            a1 = ffma2(p1, EA[r + 1], a1);
            c1 = ffma2(p1, EB[r + 1], c1);
            a2 = ffma2(p2, EA[r + 2], a2);
            c2 = ffma2(p2, EB[r + 2], c2);
            a3 = ffma2(p3, EA[r + 3], a3);
            c3 = ffma2(p3, EB[r + 3], c3);
        }
        float2 ta = unpack2(fadd2(fadd2(a0, a1), fadd2(a2, a3)));
        float2 tb = unpack2(fadd2(fadd2(c0, c1), fadd2(c2, c3)));
        tA = ta.x + ta.y;
        tB = tb.x + tb.y;
    };

    auto step = [&](float2 xe, int m, int q) {
        float tA, tB;
        matvec(tA, tB);
        float n0, n1;
        if (q == 0) {                      // chunk start: apply pending renorm
            n0 = tA * (xe.x * scale);
            n1 = tB * (xe.y * scale);
            u0    = m ? n0 : u0;
            u1    = m ? n1 : u1;
            K    += m ? pend : 0.0f;
            pend  = m ? 0.0f : pend;
            scale = m ? 1.0f : scale;
        } else {
            n0 = tA * xe.x;
            n1 = tB * xe.y;
            u0 = m ? n0 : u0;
            u1 = m ? n1 : u1;
        }
        up = pack2(u0, u1);
    };

    for (int c = 0; c < 64; c++) {
        float2 xe[8]; int mm[8];
#pragma unroll
        for (int q = 0; q < 8; q++) {
            xe[q].x = __expf(xr[q].x);
            xe[q].y = __expf(xr[q].y);
            mm[q] = mr[q];
        }
        // burst-prefetch next chunk (fire-and-forget, overlaps 8 steps)
#pragma unroll
        for (int q = 0; q < 8; q++) {
            int s = 9 + 8 * c + q;
            s = (s < S) ? s : (S - 1);
            xr[q] = em2base[(long)s * em2stride + j];
            mr[q] = mask[s * BB + b];
        }
        if (c < 63) {
#pragma unroll
            for (int q = 0; q < 8; q++) step(xe[q], mm[q], q);
            // lane-local composable renorm (off the dependence-critical path
            // of the next chunk head until its q==0 apply)
            float U = wsum(u0 + u1);
            scale *= __fdividef(1.0f, U);
            pend  += __logf(U);
        } else {
#pragma unroll
            for (int q = 0; q < 7; q++) step(xe[q], mm[q], q);
        }
    }

    // den = K + pend + log( sum(scale * u * exp(end)) )
    {
        float2 en = reinterpret_cast<const float2*>(endT)[j];
        float v = scale * (u0 * __expf(en.x) + u1 * __expf(en.y));
        float V = wsum(v);
        if (j == 0) g_den[b] = K + pend + __logf(V);
    }

    // ---- numerator (each warp: its own batch; lane j owns steps 16j..16j+15)
    {
        int tg[17]; int mk[16];
#pragma unroll
        for (int q = 0; q < 17; q++) {
            int s = 16 * j + q - 1;
            tg[q] = (s >= 0) ? (tags[s * BB + b] & (T - 1)) : 0;
        }
#pragma unroll
        for (int q = 0; q < 16; q++) mk[q] = mask[(16 * j + q) * BB + b];

        float acc = 0.0f;
        int cnt = 0;
#pragma unroll
        for (int q = 0; q < 16; q++) {
            int s = 16 * j + q;
            int t = tg[q + 1];
            cnt += (mk[q] ? 1 : 0);
            float e = em[stride * s + bT + t];
            if (s == 0)       acc += startT[t] + e;
            else if (mk[q])   acc += trans[tg[q] * T + t] + e;
        }
        acc = wsum(acc);
#pragma unroll
        for (int ofs = 16; ofs; ofs >>= 1) cnt += __shfl_xor_sync(0xffffffffu, cnt, ofs);
        if (j == 0) {
            int last = (cnt >= 1) ? (cnt - 1) : 0;
            int lt = tags[last * BB + b] & (T - 1);
            g_num[b] = acc + endT[lt];
        }
    }

    // ---- ticket-elected last block computes the mean ----
    __threadfence();
    __syncthreads();
    if (threadIdx.x == 0) {
        unsigned old;
        asm volatile("atom.global.inc.u32 %0, [%1], %2;"
                     : "=r"(old) : "l"(&g_tick), "r"((unsigned)(gridDim.x - 1))
                     : "memory");
        is_last = (old == gridDim.x - 1) ? 1u : 0u;
    }
    __syncthreads();
    if (is_last) {
        int t = threadIdx.x;
        double v = 0.0;
#pragma unroll
        for (int k = 0; k < 4; k++) {
            int idx = t * 4 + k;
            v += (double)g_num[idx] - (double)g_den[idx];
        }
#pragma unroll
        for (int ofs = 16; ofs; ofs >>= 1) v += __shfl_xor_sync(0xffffffffu, v, ofs);
        if (j == 0) dpart[warp] = v;
        __syncthreads();
        if (t == 0) {
            double tot = dpart[0] + dpart[1] + dpart[2] + dpart[3];
            out[0] = (float)(tot * (1.0 / (double)BB));
        }
    }
}

// ---------------------------------------------------------------------------
extern "C" void kernel_launch(void* const* d_in, const int* in_sizes, int n_in,
                              void* d_out, int out_size)
{
    const float* em     = (const float*)d_in[0];
    const int*   tags   = (const int*)d_in[1];
    const int*   mask   = (const int*)d_in[2];
    const float* startT = (const float*)d_in[3];
    const float* endT   = (const float*)d_in[4];
    const float* trans  = (const float*)d_in[5];

    crf_fused<<<BB / 4, 128>>>(em, tags, mask, trans, startT, endT, (float*)d_out);
}